// round 14
// baseline (speedup 1.0000x reference)
#include <cuda_runtime.h>

#define Bq   16
#define Kq   32
#define Lq   1024
#define Dq   128
#define NEWL 48

// ---- scratch ----
__device__ int   g_order[Bq * Lq];          // l indices sorted by segment, STABLE (ascending l)
__device__ int   g_off[Bq * (NEWL + 1)];
__device__ float g_tsum[Bq * NEWL];

#define NEG_INF __int_as_float(0xff800000)
#define FMAX4(a, v) { a.x = fmaxf(a.x, v.x); a.y = fmaxf(a.y, v.y); \
                      a.z = fmaxf(a.z, v.z); a.w = fmaxf(a.w, v.w); }

#define N_ALM 12288u       // almat blocks: 6,291,456 float4 / 256 / 2-per-thread

// K1: heterogeneous 256-thread blocks.
// Blocks [0,16): STABLE per-batch counting sort (threads 0..48 serial-emit in l order).
// Blocks [16, 16+12288): almat float4 streaming stores, 2 per thread.
__global__ void __launch_bounds__(256) fused_kernel(const float* __restrict__ et,
                                                    float* __restrict__ out_a) {
    const int t = threadIdx.x;

    if (blockIdx.x < Bq) {
        // ---- prep: stable counting sort of l by segment, batch b ----
        const int b = blockIdx.x;
        __shared__ float sev[Lq];            // et row, smem-resident
        __shared__ int   cnt[NEWL + 1];
        __shared__ int   off[NEWL + 1];

        #pragma unroll
        for (int r = 0; r < 4; ++r) sev[r * 256 + t] = __ldg(&et[b * Lq + r * 256 + t]);
        __syncthreads();

        if (t <= NEWL) {
            // pass 1: count members + tsum (serial scan over smem row)
            int   c  = 0;
            float ts = 0.f;
            for (int l = 0; l < Lq; ++l) {
                float tv = sev[l];
                int   s  = (tv >= 0.f && tv < 48.f) ? (int)tv : NEWL;
                if (s == t) { ++c; ts += tv; }
            }
            cnt[t] = c;
            if (t < NEWL) g_tsum[b * NEWL + t] = ts;
        }
        __syncthreads();

        if (t <= NEWL) {
            int a = 0;                        // exclusive prefix
            for (int i = 0; i < t; ++i) a += cnt[i];
            off[t] = a;
            g_off[b * (NEWL + 1) + t] = a;
        }
        __syncthreads();

        if (t < NEWL) {
            // pass 2: stable emit — members in ascending l order
            int pos = off[t];
            for (int l = 0; l < Lq; ++l) {
                float tv = sev[l];
                int   s  = (tv >= 0.f && tv < 48.f) ? (int)tv : NEWL;
                if (s == t) g_order[b * Lq + pos++] = l;
            }
        }
    } else {
        // ---- almat: (B,K,L,48) one-hot, 2 float4 streaming stores per thread ----
        unsigned g0 = (blockIdx.x - Bq) * 256u + t;
        #pragma unroll
        for (int h = 0; h < 2; ++h) {
            unsigned g   = g0 + (unsigned)h * (N_ALM * 256u);   // exact cover of 6,291,456
            unsigned row = g / 12u;              // (b,k,l) flat — u32 mul-high
            unsigned qq  = g - row * 12u;
            unsigned l   = row & (Lq - 1);
            unsigned b   = row >> 15;            // / (K*L), K*L = 2^15
            float tv = __ldg(&et[b * Lq + l]);
            int s = (tv >= 0.f && tv < 48.f) ? (int)tv : NEWL;
            float4 v = make_float4(0.f, 0.f, 0.f, 0.f);
            int o = s - (int)(qq * 4u);
            if (o >= 0 && o < 4) (&v.x)[o] = 1.f;
            __stcs(reinterpret_cast<float4*>(out_a) + g, v);
        }
    }
}

// K2: segmax + pad_mask + event_time. grid = (6, B*K), block = 256 (8 warps).
// Warp w owns segment s = bx*8 + w for column bk. Gather is now in ascending-l
// order (stable sort) -> monotone addresses; h0 via __ldcs (streamed once).
__global__ void __launch_bounds__(256) segmax_kernel(const float* __restrict__ h0,
                                                     const float* __restrict__ npm,
                                                     float* __restrict__ o_h,
                                                     float* __restrict__ o_pm,
                                                     float* __restrict__ o_et) {
    const int bk = blockIdx.y;            // 0..511
    const int b  = bk >> 5;               // K = 32
    const int w  = threadIdx.x >> 5;      // warp 0..7
    const int j  = threadIdx.x & 31;      // lane
    const int s  = blockIdx.x * 8 + w;    // this warp's segment

    const int off = g_off[b * (NEWL + 1) + s];
    const int cnt = g_off[b * (NEWL + 1) + s + 1] - off;
    const int* idx = g_order + b * Lq + off;

    const float4* base4 = reinterpret_cast<const float4*>(h0 + (size_t)bk * Lq * Dq) + j;
    float4 a0 = make_float4(NEG_INF, NEG_INF, NEG_INF, NEG_INF);
    float4 a1 = a0, a2 = a0, a3 = a0;
    int i = 0;
    for (; i + 4 <= cnt; i += 4) {
        int l0 = idx[i];     int l1 = idx[i + 1];
        int l2 = idx[i + 2]; int l3 = idx[i + 3];
        float4 v0 = __ldcs(base4 + l0 * 32);
        float4 v1 = __ldcs(base4 + l1 * 32);
        float4 v2 = __ldcs(base4 + l2 * 32);
        float4 v3 = __ldcs(base4 + l3 * 32);
        FMAX4(a0, v0); FMAX4(a1, v1); FMAX4(a2, v2); FMAX4(a3, v3);
    }
    for (; i < cnt; ++i) {
        float4 v = __ldcs(base4 + idx[i] * 32);
        FMAX4(a0, v);
    }
    FMAX4(a0, a1); FMAX4(a2, a3); FMAX4(a0, a2);
    if (cnt < Lq) {                        // include_zero (empty segs: -inf -> 0)
        float4 z = make_float4(0.f, 0.f, 0.f, 0.f);
        FMAX4(a0, z);
    }
    reinterpret_cast<float4*>(o_h)[((size_t)bk * NEWL + s) * 32 + j] = a0;

    // msum (exact: 0/1 values), lane-strided gather + shuffle reduce
    const float* mrow = npm + (size_t)bk * Lq;
    float msum = 0.f;
    for (int i2 = j; i2 < cnt; i2 += 32) msum += __ldg(&mrow[idx[i2]]);
    #pragma unroll
    for (int d = 16; d > 0; d >>= 1) msum += __shfl_down_sync(0xffffffffu, msum, d);
    if (j == 0) {
        float denom = fmaxf((float)cnt, 1.f);
        o_pm[bk * NEWL + s] = msum / denom;
        o_et[bk * NEWL + s] = g_tsum[b * NEWL + s] / denom;
    }
}

extern "C" void kernel_launch(void* const* d_in, const int* in_sizes, int n_in,
                              void* d_out, int out_size) {
    const float* h0  = (const float*)d_in[0];
    const float* et  = (const float*)d_in[1];
    const float* npm = (const float*)d_in[2];
    float* out = (float*)d_out;

    float* o_h  = out;                              // (16,32,48,128) = 3,145,728
    float* o_et = out + 3145728;                    // (16,32,48)     =    24,576
    float* o_pm = out + 3145728 + 24576;            // (16,32,48)     =    24,576
    float* o_a  = out + 3145728 + 24576 + 24576;    // (16,32,1024,48)= 25,165,824

    fused_kernel<<<Bq + N_ALM, 256>>>(et, o_a);     // prep hidden under almat
    dim3 grid(6, Bq * Kq);
    segmax_kernel<<<grid, 256>>>(h0, npm, o_h, o_pm, o_et);
}

// round 15
// speedup vs baseline: 1.2102x; 1.2102x over previous
#include <cuda_runtime.h>

#define Bq   16
#define Kq   32
#define Lq   1024
#define Dq   128
#define NEWL 48

// ---- scratch ----
__device__ int   g_order[Bq * Lq];          // l indices sorted by segment, STABLE (ascending l)
__device__ int   g_off[Bq * (NEWL + 1)];
__device__ float g_tsum[Bq * NEWL];

#define NEG_INF __int_as_float(0xff800000)
#define FMAX4(a, v) { a.x = fmaxf(a.x, v.x); a.y = fmaxf(a.y, v.y); \
                      a.z = fmaxf(a.z, v.z); a.w = fmaxf(a.w, v.w); }

#define NTHR   384
#define N_ALM  16384u      // almat blocks: 6,291,456 float4 / 384 (exact)
#define NCHK   8           // prep chunks of 128 elements

__device__ __forceinline__ int seg_of(float tv) {
    return (tv >= 0.f && tv < 48.f) ? (int)tv : NEWL;
}

// K1: heterogeneous 384-thread blocks.
// Blocks [0,16): STABLE chunked counting sort (no serial 1024-scans).
// Blocks [16, 16+16384): almat one-hot float4 stores (plain, L2-absorbed).
__global__ void __launch_bounds__(NTHR) fused_kernel(const float* __restrict__ et,
                                                     float* __restrict__ out_a) {
    const int t = threadIdx.x;

    if (blockIdx.x < Bq) {
        // ---- prep: stable counting sort of l by segment, batch b ----
        const int b = blockIdx.x;
        __shared__ float sev[Lq];                 // et row
        __shared__ int   cnt8[NCHK][NEWL + 1];    // per-chunk histogram
        __shared__ int   off[NEWL + 1];           // segment start
        __shared__ int   coff[NCHK][NEWL];        // per-(chunk,segment) start
        __shared__ float ts[NEWL];

        for (int i = t; i < NCHK * (NEWL + 1); i += NTHR)
            ((int*)cnt8)[i] = 0;
        if (t < NEWL) ts[t] = 0.f;
        for (int i = t; i < Lq; i += NTHR) sev[i] = __ldg(&et[b * Lq + i]);
        __syncthreads();

        // pass 1: chunked histogram + tsum
        for (int l = t; l < Lq; l += NTHR) {
            float tv = sev[l];
            int   s  = seg_of(tv);
            atomicAdd(&cnt8[l >> 7][s], 1);
            if (s < NEWL) atomicAdd(&ts[s], tv);
        }
        __syncthreads();

        // segment totals + exclusive prefix over segments (49 threads)
        if (t <= NEWL) {
            // totals into row 0 view via local sum
            int tot = 0;
            #pragma unroll
            for (int c = 0; c < NCHK; ++c) tot += cnt8[c][t];
            // store total in cnt8[0][t]'s place? keep separate: reuse ts? No — local.
            // exclusive prefix: thread t needs sum of totals of segments < t.
            // Write total to a shared slot first.
            off[t] = tot;                         // temporarily: totals
        }
        __syncthreads();
        __shared__ int soff[NEWL + 1];
        if (t <= NEWL) {
            int a = 0;
            for (int i = 0; i < t; ++i) a += off[i];
            soff[t] = a;
            g_off[b * (NEWL + 1) + t] = a;
            if (t < NEWL) g_tsum[b * NEWL + t] = ts[t];
        }
        __syncthreads();

        // per-(segment,chunk) start offsets: 48*8 = 384 threads exactly
        {
            int s = t >> 3, c = t & 7;            // s in [0,48), c in [0,8)
            int a = soff[s];
            for (int cc = 0; cc < c; ++cc) a += cnt8[cc][s];
            coff[c][s] = a;
        }
        __syncthreads();

        // emit: thread (s,c) scans its 128-element chunk in ascending l
        {
            int s = t >> 3, c = t & 7;
            int pos = coff[c][s];
            int l0 = c << 7;
            #pragma unroll 4
            for (int l = l0; l < l0 + 128; ++l) {
                if (seg_of(sev[l]) == s) g_order[b * Lq + pos++] = l;
            }
        }
    } else {
        // ---- almat: (B,K,L,48) one-hot, float4 stores, 32-bit indexing ----
        unsigned g   = (blockIdx.x - Bq) * (unsigned)NTHR + t;   // exact cover
        unsigned row = g / 12u;               // (b,k,l) flat — u32 mul-high
        unsigned qq  = g - row * 12u;
        unsigned l   = row & (Lq - 1);
        unsigned b   = row >> 15;             // / (K*L), K*L = 2^15
        float tv = __ldg(&et[b * Lq + l]);
        int s = seg_of(tv);
        float4 v = make_float4(0.f, 0.f, 0.f, 0.f);
        int o = s - (int)(qq * 4u);
        if (o >= 0 && o < 4) (&v.x)[o] = 1.f;
        reinterpret_cast<float4*>(out_a)[g] = v;
    }
}

// K2: segmax + pad_mask + event_time. grid = (6, B*K), block = 256 (8 warps).
// Warp w owns segment s = bx*8 + w for column bk. Gather in ascending-l order;
// h0 via __ldcs (streamed once, keep L1 for the index stream).
__global__ void __launch_bounds__(256) segmax_kernel(const float* __restrict__ h0,
                                                     const float* __restrict__ npm,
                                                     float* __restrict__ o_h,
                                                     float* __restrict__ o_pm,
                                                     float* __restrict__ o_et) {
    const int bk = blockIdx.y;            // 0..511
    const int b  = bk >> 5;               // K = 32
    const int w  = threadIdx.x >> 5;      // warp 0..7
    const int j  = threadIdx.x & 31;      // lane
    const int s  = blockIdx.x * 8 + w;    // this warp's segment

    const int off = g_off[b * (NEWL + 1) + s];
    const int cnt = g_off[b * (NEWL + 1) + s + 1] - off;
    const int* idx = g_order + b * Lq + off;

    const float4* base4 = reinterpret_cast<const float4*>(h0 + (size_t)bk * Lq * Dq) + j;
    float4 a0 = make_float4(NEG_INF, NEG_INF, NEG_INF, NEG_INF);
    float4 a1 = a0, a2 = a0, a3 = a0;
    int i = 0;
    for (; i + 4 <= cnt; i += 4) {
        int l0 = idx[i];     int l1 = idx[i + 1];
        int l2 = idx[i + 2]; int l3 = idx[i + 3];
        float4 v0 = __ldcs(base4 + l0 * 32);
        float4 v1 = __ldcs(base4 + l1 * 32);
        float4 v2 = __ldcs(base4 + l2 * 32);
        float4 v3 = __ldcs(base4 + l3 * 32);
        FMAX4(a0, v0); FMAX4(a1, v1); FMAX4(a2, v2); FMAX4(a3, v3);
    }
    for (; i < cnt; ++i) {
        float4 v = __ldcs(base4 + idx[i] * 32);
        FMAX4(a0, v);
    }
    FMAX4(a0, a1); FMAX4(a2, a3); FMAX4(a0, a2);
    if (cnt < Lq) {                        // include_zero (empty segs: -inf -> 0)
        float4 z = make_float4(0.f, 0.f, 0.f, 0.f);
        FMAX4(a0, z);
    }
    reinterpret_cast<float4*>(o_h)[((size_t)bk * NEWL + s) * 32 + j] = a0;

    // msum (exact: 0/1 values), lane-strided gather + shuffle reduce
    const float* mrow = npm + (size_t)bk * Lq;
    float msum = 0.f;
    for (int i2 = j; i2 < cnt; i2 += 32) msum += __ldg(&mrow[idx[i2]]);
    #pragma unroll
    for (int d = 16; d > 0; d >>= 1) msum += __shfl_down_sync(0xffffffffu, msum, d);
    if (j == 0) {
        float denom = fmaxf((float)cnt, 1.f);
        o_pm[bk * NEWL + s] = msum / denom;
        o_et[bk * NEWL + s] = g_tsum[b * NEWL + s] / denom;
    }
}

extern "C" void kernel_launch(void* const* d_in, const int* in_sizes, int n_in,
                              void* d_out, int out_size) {
    const float* h0  = (const float*)d_in[0];
    const float* et  = (const float*)d_in[1];
    const float* npm = (const float*)d_in[2];
    float* out = (float*)d_out;

    float* o_h  = out;                              // (16,32,48,128) = 3,145,728
    float* o_et = out + 3145728;                    // (16,32,48)     =    24,576
    float* o_pm = out + 3145728 + 24576;            // (16,32,48)     =    24,576
    float* o_a  = out + 3145728 + 24576 + 24576;    // (16,32,1024,48)= 25,165,824

    fused_kernel<<<Bq + N_ALM, NTHR>>>(et, o_a);    // prep hidden under almat
    dim3 grid(6, Bq * Kq);
    segmax_kernel<<<grid, 256>>>(h0, npm, o_h, o_pm, o_et);
}